// round 10
// baseline (speedup 1.0000x reference)
#include <cuda_runtime.h>
#include <cstdint>

#define NS 50000
#define NT 50000
#define NE 800000
#define D  128
#define NTOT (NS + NT)
#define SCAN_BS 1024
#define NBLK ((NT + SCAN_BS - 1) / SCAN_BS)   // 49

#define TILE_M 128
#define KC 32
#define GEMM_BLKS ((NS + TILE_M - 1) / TILE_M)        // 391 (covers s-rows; t same count)
#define AGG_BLKS  ((NT * 32 + 255) / 256)             // 6250

// ---------------- scratch (device globals; no allocation allowed) ----------------
__device__ int   g_deg[NT];
__device__ int   g_cursor[NT];
__device__ int   g_rowstart[NT];
__device__ int   g_blocksum[64];
__device__ int   g_blockoff[64];
__device__ int   g_srcidx[NE];
__device__ __align__(16) float g_agg[(size_t)NT * D];

// packed fp32x2 FMA (Blackwell FFMA2) — exact fp32, 2x throughput
__device__ __forceinline__ void fma2(unsigned long long& d,
                                     unsigned long long a,
                                     unsigned long long b) {
    asm("fma.rn.f32x2 %0, %1, %2, %0;" : "+l"(d) : "l"(a), "l"(b));
}

// ---------------- K0: zero counters ----------------
__global__ void k_zero() {
    int i = blockIdx.x * blockDim.x + threadIdx.x;
    if (i < NT) { g_deg[i] = 0; g_cursor[i] = 0; }
}

// ---------------- K1: in-degree histogram (edge_index is int32) ----------------
__global__ void k_count(const int* __restrict__ ei) {
    int e = blockIdx.x * blockDim.x + threadIdx.x;
    if (e < NE) atomicAdd(&g_deg[ei[NE + e]], 1);
}

// ---------------- K2a: per-block exclusive scan (warp-shuffle) ----------------
__global__ __launch_bounds__(SCAN_BS) void k_scanA() {
    int t = threadIdx.x, b = blockIdx.x;
    int idx = b * SCAN_BS + t;
    int v = (idx < NT) ? g_deg[idx] : 0;
    int lane = t & 31, wid = t >> 5;
    int x = v;
    #pragma unroll
    for (int off = 1; off < 32; off <<= 1) {
        int y = __shfl_up_sync(0xffffffffu, x, off);
        if (lane >= off) x += y;                  // inclusive within warp
    }
    __shared__ int wsum[32];
    if (lane == 31) wsum[wid] = x;
    __syncthreads();
    if (wid == 0) {
        int s = wsum[lane];
        int z = s;
        #pragma unroll
        for (int off = 1; off < 32; off <<= 1) {
            int y = __shfl_up_sync(0xffffffffu, z, off);
            if (lane >= off) z += y;
        }
        wsum[lane] = z - s;                        // exclusive warp offsets
    }
    __syncthreads();
    int incl = x + wsum[wid];
    if (idx < NT) g_rowstart[idx] = incl - v;
    if (t == SCAN_BS - 1) g_blocksum[b] = incl;
}

// ---------------- K2b: scan of block sums (64 entries) ----------------
__global__ void k_scanB() {
    int t = threadIdx.x;            // 64 threads
    int v = (t < NBLK) ? g_blocksum[t] : 0;
    int x = v;
    #pragma unroll
    for (int off = 1; off < 32; off <<= 1) {
        int y = __shfl_up_sync(0xffffffffu, x, off);
        if ((t & 31) >= off) x += y;
    }
    __shared__ int warp0_total;
    if (t == 31) warp0_total = x;
    __syncthreads();
    int excl = x - v + ((t >= 32) ? warp0_total : 0);
    if (t < NBLK) g_blockoff[t] = excl;
}

// ---------------- K3: fill CSR edge lists ----------------
__global__ void k_fill(const int* __restrict__ ei) {
    int e = blockIdx.x * blockDim.x + threadIdx.x;
    if (e >= NE) return;
    int src = ei[e];
    int dst = ei[NE + e];
    int base = __ldg(&g_rowstart[dst]) + __ldg(&g_blockoff[dst >> 10]);
    int pos  = base + atomicAdd(&g_cursor[dst], 1);
    g_srcidx[pos] = src;
}

// ================= shared GEMM tile body (FFMA2) =================
// computes out[outRowBase + r] = relu(A[aRowBase + r] @ W) for r in [0,TILE_M)
// rows with aRowBase + r >= aLimit are skipped (A read as 0, no store)
__device__ __forceinline__ void gemm_tile(const float* __restrict__ A,
                                          int aRowBase, int aLimit,
                                          const float* __restrict__ Wm,
                                          float* __restrict__ out,
                                          int outRowBase) {
    __shared__ float2 As2[TILE_M][KC + 1];   // splatted A, padded pitch
    __shared__ float4 Ws4[KC][32];           // B tile: 32 float4 per k-row

    int tid = threadIdx.x;
    int tx  = tid & 7;          // 8 col-groups
    int ty  = tid >> 3;         // 32 row-groups of 4

    unsigned long long acc[4][8];            // 4 rows x 8 f32x2 pairs (16 cols)
    #pragma unroll
    for (int i = 0; i < 4; i++)
        #pragma unroll
        for (int j = 0; j < 8; j++) acc[i][j] = 0ull;

    for (int kb = 0; kb < D; kb += KC) {
        #pragma unroll
        for (int l = 0; l < 4; l++) {
            int lin = tid + l * 256;          // 0..1023
            int r   = lin >> 3;               // 8 float4 per row
            int c4  = lin & 7;
            int ar  = aRowBase + r;
            float4 v = make_float4(0.f, 0.f, 0.f, 0.f);
            if (ar < aLimit)
                v = reinterpret_cast<const float4*>(A + (size_t)ar * D + kb)[c4];
            As2[r][c4 * 4 + 0] = make_float2(v.x, v.x);
            As2[r][c4 * 4 + 1] = make_float2(v.y, v.y);
            As2[r][c4 * 4 + 2] = make_float2(v.z, v.z);
            As2[r][c4 * 4 + 3] = make_float2(v.w, v.w);
        }
        #pragma unroll
        for (int l = 0; l < 4; l++) {
            int lin = tid + l * 256;
            int r   = lin >> 5;               // 32 float4 per row
            int c4  = lin & 31;
            Ws4[r][c4] = reinterpret_cast<const float4*>(Wm + (size_t)(kb + r) * D)[c4];
        }
        __syncthreads();

        #pragma unroll
        for (int k = 0; k < KC; k++) {
            unsigned long long a[4];
            #pragma unroll
            for (int i = 0; i < 4; i++) {
                float2 af = As2[ty * 4 + i][k];
                a[i] = *reinterpret_cast<unsigned long long*>(&af);
            }
            #pragma unroll
            for (int j = 0; j < 4; j++) {
                float4 w = Ws4[k][tx + 8 * j];
                unsigned long long b0 = *reinterpret_cast<unsigned long long*>(&w.x);
                unsigned long long b1 = *reinterpret_cast<unsigned long long*>(&w.z);
                #pragma unroll
                for (int i = 0; i < 4; i++) {
                    fma2(acc[i][2 * j + 0], a[i], b0);
                    fma2(acc[i][2 * j + 1], a[i], b1);
                }
            }
        }
        __syncthreads();
    }

    #pragma unroll
    for (int i = 0; i < 4; i++) {
        int r = ty * 4 + i;
        if (aRowBase + r < aLimit) {
            float* po = out + (size_t)(outRowBase + r) * D;
            #pragma unroll
            for (int j = 0; j < 4; j++) {
                float2 p0 = *reinterpret_cast<float2*>(&acc[i][2 * j + 0]);
                float2 p1 = *reinterpret_cast<float2*>(&acc[i][2 * j + 1]);
                float4 o;
                o.x = fmaxf(p0.x, 0.f); o.y = fmaxf(p0.y, 0.f);
                o.z = fmaxf(p1.x, 0.f); o.w = fmaxf(p1.y, 0.f);
                *reinterpret_cast<float4*>(po + (tx + 8 * j) * 4) = o;
            }
        }
    }
}

// ---------------- K4: FUSED  gemm_s (xs@W)  ∥  agg (CSR gather) ----------------
// blocks [0, GEMM_BLKS): GEMM over x_s rows (independent of the graph)
// blocks [GEMM_BLKS, GEMM_BLKS+AGG_BLKS): warp-per-row gather aggregation
__global__ __launch_bounds__(256, 2) void k_agg_gemms(const float* __restrict__ xs,
                                                      const float* __restrict__ xt,
                                                      const float* __restrict__ Wm,
                                                      float* __restrict__ out) {
    if (blockIdx.x < GEMM_BLKS) {
        int rowBase = blockIdx.x * TILE_M;
        gemm_tile(xs, rowBase, NS, Wm, out, rowBase);
        return;
    }
    // ---- aggregation path ----
    int b    = blockIdx.x - GEMM_BLKS;
    int w    = (b * 256 + threadIdx.x) >> 5;
    int lane = threadIdx.x & 31;
    if (w >= NT) return;
    int cnt  = g_deg[w];
    int base = g_rowstart[w] + g_blockoff[w >> 10];

    float4 acc = make_float4(0.f, 0.f, 0.f, 0.f);
    for (int e0 = 0; e0 < cnt; e0 += 16) {
        int s = 0;
        if (lane < 16 && e0 + lane < cnt) s = __ldg(&g_srcidx[base + e0 + lane]);
        int m = min(16, cnt - e0);
        for (int i = 0; i < m; i++) {
            int src = __shfl_sync(0xffffffffu, s, i);
            float4 v = __ldg(reinterpret_cast<const float4*>(xs) + (size_t)src * 32 + lane);
            acc.x += v.x; acc.y += v.y; acc.z += v.z; acc.w += v.w;
        }
    }
    float degp1 = (float)(cnt + 1);
    float dinv  = rsqrtf(degp1);
    float inv   = 1.0f / degp1;
    float4 tv = __ldg(reinterpret_cast<const float4*>(xt) + (size_t)w * 32 + lane);
    acc.x = acc.x * dinv + tv.x * inv;
    acc.y = acc.y * dinv + tv.y * inv;
    acc.z = acc.z * dinv + tv.z * inv;
    acc.w = acc.w * dinv + tv.w * inv;
    reinterpret_cast<float4*>(g_agg)[(size_t)w * 32 + lane] = acc;
}

// ---------------- K5: gemm_t (g_agg @ W) ----------------
__global__ __launch_bounds__(256, 2) void k_gemm_t(const float* __restrict__ Wm,
                                                   float* __restrict__ out) {
    int rowBase = blockIdx.x * TILE_M;
    gemm_tile(g_agg, rowBase, NT, Wm, out, NS + rowBase);
}

// ---------------- launch ----------------
extern "C" void kernel_launch(void* const* d_in, const int* in_sizes, int n_in,
                              void* d_out, int out_size) {
    const int*   ei = (const int*)d_in[0];     // [2, E] int32 (JAX x64 disabled)
    const float* xs = (const float*)d_in[1];   // [NS, 128]
    const float* xt = (const float*)d_in[2];   // [NT, 128]
    const float* W  = (const float*)d_in[3];   // [128, 128]
    float*      out = (float*)d_out;           // [NS+NT, 128]

    k_zero <<<(NT + 255) / 256, 256>>>();
    k_count<<<(NE + 255) / 256, 256>>>(ei);
    k_scanA<<<NBLK, SCAN_BS>>>();
    k_scanB<<<1, 64>>>();
    k_fill <<<(NE + 255) / 256, 256>>>(ei);
    k_agg_gemms<<<GEMM_BLKS + AGG_BLKS, 256>>>(xs, xt, W, out);
    k_gemm_t   <<<GEMM_BLKS, 256>>>(W, out);
}

// round 11
// speedup vs baseline: 1.9106x; 1.9106x over previous
#include <cuda_runtime.h>
#include <cstdint>

#define NS 50000
#define NT 50000
#define NE 800000
#define D  128
#define NTOT (NS + NT)
#define SCAN_BS 1024
#define NBLK ((NT + SCAN_BS - 1) / SCAN_BS)   // 49

// ---------------- scratch (device globals; no allocation allowed) ----------------
__device__ int   g_deg[NT];
__device__ int   g_cursor[NT];
__device__ int   g_rowstart[NT];
__device__ int   g_blocksum[64];
__device__ int   g_blockoff[64];
__device__ int   g_srcidx[NE];
__device__ __align__(16) float g_agg[(size_t)NT * D];

// ---------------- K0: zero counters ----------------
__global__ void k_zero() {
    int i = blockIdx.x * blockDim.x + threadIdx.x;
    if (i < NT) { g_deg[i] = 0; g_cursor[i] = 0; }
}

// ---------------- K1: in-degree histogram (edge_index is int32) ----------------
__global__ void k_count(const int* __restrict__ ei) {
    int e = blockIdx.x * blockDim.x + threadIdx.x;
    if (e < NE) atomicAdd(&g_deg[ei[NE + e]], 1);
}

// ---------------- K2a: per-block exclusive scan (warp-shuffle) ----------------
__global__ __launch_bounds__(SCAN_BS) void k_scanA() {
    int t = threadIdx.x, b = blockIdx.x;
    int idx = b * SCAN_BS + t;
    int v = (idx < NT) ? g_deg[idx] : 0;
    int lane = t & 31, wid = t >> 5;
    int x = v;
    #pragma unroll
    for (int off = 1; off < 32; off <<= 1) {
        int y = __shfl_up_sync(0xffffffffu, x, off);
        if (lane >= off) x += y;                  // inclusive within warp
    }
    __shared__ int wsum[32];
    if (lane == 31) wsum[wid] = x;
    __syncthreads();
    if (wid == 0) {
        int s = wsum[lane];
        int z = s;
        #pragma unroll
        for (int off = 1; off < 32; off <<= 1) {
            int y = __shfl_up_sync(0xffffffffu, z, off);
            if (lane >= off) z += y;
        }
        wsum[lane] = z - s;                        // exclusive warp offsets
    }
    __syncthreads();
    int incl = x + wsum[wid];
    if (idx < NT) g_rowstart[idx] = incl - v;
    if (t == SCAN_BS - 1) g_blocksum[b] = incl;
}

// ---------------- K2b: scan of block sums (64 entries) ----------------
__global__ void k_scanB() {
    int t = threadIdx.x;            // 64 threads
    int v = (t < NBLK) ? g_blocksum[t] : 0;
    int x = v;
    #pragma unroll
    for (int off = 1; off < 32; off <<= 1) {
        int y = __shfl_up_sync(0xffffffffu, x, off);
        if ((t & 31) >= off) x += y;
    }
    __shared__ int warp0_total;
    if (t == 31) warp0_total = x;
    __syncthreads();
    int excl = x - v + ((t >= 32) ? warp0_total : 0);
    if (t < NBLK) g_blockoff[t] = excl;
}

// ---------------- K3: fill CSR edge lists ----------------
__global__ void k_fill(const int* __restrict__ ei) {
    int e = blockIdx.x * blockDim.x + threadIdx.x;
    if (e >= NE) return;
    int src = ei[e];
    int dst = ei[NE + e];
    int base = __ldg(&g_rowstart[dst]) + __ldg(&g_blockoff[dst >> 10]);
    int pos  = base + atomicAdd(&g_cursor[dst], 1);
    g_srcidx[pos] = src;
}

// ---------------- K4: gather aggregation (atomic-free, standalone = high occ) --
__global__ __launch_bounds__(256) void k_agg(const float* __restrict__ xs,
                                             const float* __restrict__ xt) {
    int w    = (blockIdx.x * blockDim.x + threadIdx.x) >> 5;
    int lane = threadIdx.x & 31;
    if (w >= NT) return;
    int cnt  = g_deg[w];
    int base = g_rowstart[w] + g_blockoff[w >> 10];

    float4 acc = make_float4(0.f, 0.f, 0.f, 0.f);
    for (int e0 = 0; e0 < cnt; e0 += 16) {
        int s = 0;
        if (lane < 16 && e0 + lane < cnt) s = __ldg(&g_srcidx[base + e0 + lane]);
        int m = min(16, cnt - e0);
        for (int i = 0; i < m; i++) {
            int src = __shfl_sync(0xffffffffu, s, i);
            float4 v = __ldg(reinterpret_cast<const float4*>(xs) + (size_t)src * 32 + lane);
            acc.x += v.x; acc.y += v.y; acc.z += v.z; acc.w += v.w;
        }
    }
    float degp1 = (float)(cnt + 1);
    float dinv  = rsqrtf(degp1);
    float inv   = 1.0f / degp1;
    float4 tv = __ldg(reinterpret_cast<const float4*>(xt) + (size_t)w * 32 + lane);
    acc.x = acc.x * dinv + tv.x * inv;
    acc.y = acc.y * dinv + tv.y * inv;
    acc.z = acc.z * dinv + tv.z * inv;
    acc.w = acc.w * dinv + tv.w * inv;
    reinterpret_cast<float4*>(g_agg)[(size_t)w * 32 + lane] = acc;
}

// ---------------- K5: tensor-core GEMM (tf32 mma.sync) + ReLU ----------------
// tile 128x128, 256 threads (8 warps), warp w -> rows [16w, 16w+16)
// smem pitches chosen so fragment loads hit 32 distinct banks.
#define GTILE_M 128
#define GKC 32
#define A_PITCH 36
#define B_PITCH 136

__device__ __forceinline__ uint32_t f2tf32(float f) {
    uint32_t u;
    asm("cvt.rna.tf32.f32 %0, %1;" : "=r"(u) : "f"(f));
    return u;
}

__device__ __forceinline__ void mma_tf32(float c[4], uint32_t a0, uint32_t a1,
                                         uint32_t a2, uint32_t a3,
                                         uint32_t b0, uint32_t b1) {
    asm("mma.sync.aligned.m16n8k8.row.col.f32.tf32.tf32.f32 "
        "{%0,%1,%2,%3}, {%4,%5,%6,%7}, {%8,%9}, {%0,%1,%2,%3};"
        : "+f"(c[0]), "+f"(c[1]), "+f"(c[2]), "+f"(c[3])
        : "r"(a0), "r"(a1), "r"(a2), "r"(a3), "r"(b0), "r"(b1));
}

__global__ __launch_bounds__(256, 2) void k_gemm(const float* __restrict__ xs,
                                                 const float* __restrict__ Wm,
                                                 float* __restrict__ out) {
    __shared__ uint32_t As[GTILE_M * A_PITCH];
    __shared__ uint32_t Bs[GKC * B_PITCH];

    int tid  = threadIdx.x;
    int warp = tid >> 5, lane = tid & 31;
    int q = lane >> 2, r = lane & 3;        // fragment coords
    int rowBase = blockIdx.x * GTILE_M;
    int r0 = warp * 16;

    float c[16][4];
    #pragma unroll
    for (int j = 0; j < 16; j++)
        #pragma unroll
        for (int i = 0; i < 4; i++) c[j][i] = 0.f;

    for (int kb = 0; kb < D; kb += GKC) {
        // ---- load A tile (128 x 32 floats), convert to tf32 bits ----
        #pragma unroll
        for (int l = 0; l < 4; l++) {
            int lin = tid + l * 256;          // 0..1023
            int rr  = lin >> 3;               // 8 float4 per row
            int c4  = lin & 7;
            int g   = rowBase + rr;
            float4 v = make_float4(0.f, 0.f, 0.f, 0.f);
            if (g < NS) {
                v = reinterpret_cast<const float4*>(xs + (size_t)g * D + kb)[c4];
            } else if (g < NTOT) {
                v = reinterpret_cast<const float4*>(g_agg + (size_t)(g - NS) * D + kb)[c4];
            }
            uint32_t* p = &As[rr * A_PITCH + c4 * 4];
            p[0] = f2tf32(v.x); p[1] = f2tf32(v.y);
            p[2] = f2tf32(v.z); p[3] = f2tf32(v.w);
        }
        // ---- load B tile (32 x 128 floats) ----
        #pragma unroll
        for (int l = 0; l < 4; l++) {
            int lin = tid + l * 256;
            int rk  = lin >> 5;               // 32 float4 per row
            int c4  = lin & 31;
            float4 v = reinterpret_cast<const float4*>(Wm + (size_t)(kb + rk) * D)[c4];
            uint32_t* p = &Bs[rk * B_PITCH + c4 * 4];
            p[0] = f2tf32(v.x); p[1] = f2tf32(v.y);
            p[2] = f2tf32(v.z); p[3] = f2tf32(v.w);
        }
        __syncthreads();

        // ---- compute: 4 k-steps of 8 ----
        #pragma unroll
        for (int ks = 0; ks < GKC; ks += 8) {
            uint32_t a0 = As[(r0 + q) * A_PITCH + ks + r];
            uint32_t a1 = As[(r0 + 8 + q) * A_PITCH + ks + r];
            uint32_t a2 = As[(r0 + q) * A_PITCH + ks + 4 + r];
            uint32_t a3 = As[(r0 + 8 + q) * A_PITCH + ks + 4 + r];
            #pragma unroll
            for (int j = 0; j < 16; j++) {
                uint32_t b0 = Bs[(ks + r) * B_PITCH + j * 8 + q];
                uint32_t b1 = Bs[(ks + 4 + r) * B_PITCH + j * 8 + q];
                mma_tf32(c[j], a0, a1, a2, a3, b0, b1);
            }
        }
        __syncthreads();
    }

    // ---- epilogue: ReLU + float2 stores ----
    int rowA = rowBase + r0 + q;
    int rowB = rowA + 8;
    #pragma unroll
    for (int j = 0; j < 16; j++) {
        int n = j * 8 + 2 * r;
        if (rowA < NTOT) {
            float2 o = make_float2(fmaxf(c[j][0], 0.f), fmaxf(c[j][1], 0.f));
            *reinterpret_cast<float2*>(out + (size_t)rowA * D + n) = o;
        }
        if (rowB < NTOT) {
            float2 o = make_float2(fmaxf(c[j][2], 0.f), fmaxf(c[j][3], 0.f));
            *reinterpret_cast<float2*>(out + (size_t)rowB * D + n) = o;
        }
    }
}

// ---------------- launch ----------------
extern "C" void kernel_launch(void* const* d_in, const int* in_sizes, int n_in,
                              void* d_out, int out_size) {
    const int*   ei = (const int*)d_in[0];     // [2, E] int32 (JAX x64 disabled)
    const float* xs = (const float*)d_in[1];   // [NS, 128]
    const float* xt = (const float*)d_in[2];   // [NT, 128]
    const float* W  = (const float*)d_in[3];   // [128, 128]
    float*      out = (float*)d_out;           // [NS+NT, 128]

    k_zero <<<(NT + 255) / 256, 256>>>();
    k_count<<<(NE + 255) / 256, 256>>>(ei);
    k_scanA<<<NBLK, SCAN_BS>>>();
    k_scanB<<<1, 64>>>();
    k_fill <<<(NE + 255) / 256, 256>>>(ei);
    k_agg  <<<(NT * 32 + 255) / 256, 256>>>(xs, xt);
    k_gemm <<<(NTOT + GTILE_M - 1) / GTILE_M, 256>>>(xs, W, out);
}